// round 1
// baseline (speedup 1.0000x reference)
#include <cuda_runtime.h>
#include <cstdint>
#include <math.h>

#define N_ROWS 65536
#define DIM    512
#define KCODES 1024
#define BM     64
#define BN     128
#define KT     16
#define NCHUNK (KCODES / BN)   // 8
#define NKT    (DIM / KT)      // 32

#define QUANT_OFF 1
#define PERP_OFF  (1 + N_ROWS * DIM)           // 33554433
#define ENC_OFF   (2 + (size_t)N_ROWS * DIM)   // 33554434

// ---- scratch (no allocations allowed) ----
__device__ float  g_wnorm[KCODES];
__device__ int    g_idx[N_ROWS];
__device__ int    g_counts[KCODES];
__device__ double g_sse;

// ============================================================
// prep: wnorm per code + zero counts/sse
// ============================================================
__global__ void vq_prep_kernel(const float* __restrict__ W) {
    int w = threadIdx.x >> 5, lane = threadIdx.x & 31;
    int code = blockIdx.x * 8 + w;
    const float* row = W + (size_t)code * DIM;
    float s = 0.f;
#pragma unroll
    for (int t = 0; t < DIM / 32; t++) { float v = row[lane + t * 32]; s += v * v; }
#pragma unroll
    for (int o = 16; o > 0; o >>= 1) s += __shfl_down_sync(0xffffffffu, s, o);
    if (lane == 0) g_wnorm[code] = s;
    if (blockIdx.x == 0) {
        for (int i = threadIdx.x; i < KCODES; i += blockDim.x) g_counts[i] = 0;
        if (threadIdx.x == 0) g_sse = 0.0;
    }
}

// ============================================================
// main: fused GEMM + argmin.
// Block: 256 threads, 64 rows x all 1024 codes (8 chunks of 128).
// A tile (64x512) resident in padded smem; B double-buffered via regs.
// d = (xn + wn) - 2*dot  (replicates reference fp32 formula exactly).
// ============================================================
// smem float offsets
#define AS_OFF   0          // [64][516]
#define BS_OFF   33024      // [2][16][136]
#define WN_OFF   37376      // [128]
#define XN_OFF   37504      // [64]
#define PART_OFF 37568      // [64][4]
#define BEST_OFF 37824      // [64] ull (8B aligned: 37824*4 % 8 == 0)
#define SMEM_FLOATS 37952   // 151808 bytes

__global__ void __launch_bounds__(256, 1)
vq_argmin_kernel(const float* __restrict__ X, const float* __restrict__ W) {
    extern __shared__ float sm[];
    float* As   = sm + AS_OFF;
    float* Bs   = sm + BS_OFF;
    float* sWn  = sm + WN_OFF;
    float* sXn  = sm + XN_OFF;
    float* sPart= sm + PART_OFF;
    unsigned long long* sBest = (unsigned long long*)(sm + BEST_OFF);

    const int tid = threadIdx.x;
    const int r0  = blockIdx.x * BM;

    // ---- load A tile 64x512 -> padded smem (stride 516) ----
    {
        const float4* Xg = (const float4*)(X + (size_t)r0 * DIM);
#pragma unroll
        for (int i = 0; i < 32; i++) {
            int f = tid + i * 256;          // 0..8191 float4s
            int row = f >> 7;
            int c4  = f & 127;
            float4 v = Xg[row * 128 + c4];
            *((float4*)(As + row * 516 + c4 * 4)) = v;
        }
    }
    __syncthreads();

    // ---- xnorm per row (4 partials then combine) ----
    {
        int row = tid >> 2, part = tid & 3;
        const float* ap = As + row * 516 + part * 128;
        float s = 0.f;
#pragma unroll 8
        for (int t = 0; t < 128; t++) { float v = ap[t]; s += v * v; }
        sPart[row * 4 + part] = s;
    }
    if (tid < BM) sBest[tid] = 0xFFFFFFFFFFFFFFFFull;
    __syncthreads();
    if (tid < BM) {
        float* p = sPart + tid * 4;
        sXn[tid] = (p[0] + p[1]) + (p[2] + p[3]);
    }

    const int tr = tid >> 4, tc = tid & 15;

    for (int chunk = 0; chunk < NCHUNK; chunk++) {
        const int c0 = chunk * BN;
        __syncthreads();                 // sXn ready / Bs+sWn reuse safe
        if (tid < BN) sWn[tid] = g_wnorm[c0 + tid];

        // prologue: stage kt=0 B tile (transpose to Bs[k][col], stride 136)
#pragma unroll
        for (int h = 0; h < 2; h++) {
            int f = tid + h * 256;       // 0..511 float4s
            int code = f >> 2, kq = (f & 3) * 4;
            float4 v = *(const float4*)(W + (size_t)(c0 + code) * DIM + kq);
            float* dst = Bs;
            dst[(kq + 0) * 136 + code] = v.x;
            dst[(kq + 1) * 136 + code] = v.y;
            dst[(kq + 2) * 136 + code] = v.z;
            dst[(kq + 3) * 136 + code] = v.w;
        }
        __syncthreads();

        float acc[4][8];
#pragma unroll
        for (int i = 0; i < 4; i++)
#pragma unroll
            for (int j = 0; j < 8; j++) acc[i][j] = 0.f;

        for (int kt = 0; kt < NKT; kt++) {
            const int cur = kt & 1;
            float4 pre0, pre1;
            const bool more = (kt + 1 < NKT);
            if (more) {                  // prefetch next tile into regs
                int f0 = tid, f1 = tid + 256;
                int code0 = f0 >> 2, kq0 = (f0 & 3) * 4;
                int code1 = f1 >> 2, kq1 = (f1 & 3) * 4;
                pre0 = *(const float4*)(W + (size_t)(c0 + code0) * DIM + (kt + 1) * KT + kq0);
                pre1 = *(const float4*)(W + (size_t)(c0 + code1) * DIM + (kt + 1) * KT + kq1);
            }
            const float* B = Bs + cur * 2176;
#pragma unroll
            for (int kk4 = 0; kk4 < KT; kk4 += 4) {
                float4 av[4];
#pragma unroll
                for (int i = 0; i < 4; i++)
                    av[i] = *(const float4*)(As + (tr * 4 + i) * 516 + kt * KT + kk4);
#pragma unroll
                for (int u = 0; u < 4; u++) {
                    const float* brow = B + (kk4 + u) * 136;
                    float4 b0 = *(const float4*)(brow + tc * 4);
                    float4 b1 = *(const float4*)(brow + 64 + tc * 4);
#pragma unroll
                    for (int i = 0; i < 4; i++) {
                        float a = (u == 0) ? av[i].x : (u == 1) ? av[i].y
                                : (u == 2) ? av[i].z : av[i].w;
                        acc[i][0] += a * b0.x; acc[i][1] += a * b0.y;
                        acc[i][2] += a * b0.z; acc[i][3] += a * b0.w;
                        acc[i][4] += a * b1.x; acc[i][5] += a * b1.y;
                        acc[i][6] += a * b1.z; acc[i][7] += a * b1.w;
                    }
                }
            }
            if (more) {
                __syncthreads();         // all readers done with buffer cur^1
                float* dst = Bs + (cur ^ 1) * 2176;
                int f0 = tid, f1 = tid + 256;
                int code0 = f0 >> 2, kq0 = (f0 & 3) * 4;
                int code1 = f1 >> 2, kq1 = (f1 & 3) * 4;
                dst[(kq0 + 0) * 136 + code0] = pre0.x;
                dst[(kq0 + 1) * 136 + code0] = pre0.y;
                dst[(kq0 + 2) * 136 + code0] = pre0.z;
                dst[(kq0 + 3) * 136 + code0] = pre0.w;
                dst[(kq1 + 0) * 136 + code1] = pre1.x;
                dst[(kq1 + 1) * 136 + code1] = pre1.y;
                dst[(kq1 + 2) * 136 + code1] = pre1.z;
                dst[(kq1 + 3) * 136 + code1] = pre1.w;
                __syncthreads();
            }
        }

        // ---- epilogue: distances + per-row argmin (first-index ties) ----
#pragma unroll
        for (int i = 0; i < 4; i++) {
            int row = tr * 4 + i;
            float xn = sXn[row];
            unsigned long long best = 0xFFFFFFFFFFFFFFFFull;
#pragma unroll
            for (int j = 0; j < 8; j++) {
                int col = (j < 4) ? (tc * 4 + j) : (64 + tc * 4 + (j - 4));
                float d = (xn + sWn[col]) - 2.0f * acc[i][j];   // reference formula
                unsigned key = __float_as_uint(d);
                key = (key & 0x80000000u) ? ~key : (key | 0x80000000u);
                unsigned long long pk =
                    ((unsigned long long)key << 32) | (unsigned)(c0 + col);
                if (pk < best) best = pk;
            }
            atomicMin(&sBest[row], best);
        }
    }

    __syncthreads();
    if (tid < BM) {
        int idx = (int)(sBest[tid] & 0xFFFFFFFFu);
        g_idx[r0 + tid] = idx;
        atomicAdd(&g_counts[idx], 1);
    }
}

// ============================================================
// output: quantized_st + encodings + SSE partials
// grid 1024 x 256, 64 rows per block (1 global double-atomic per block)
// ============================================================
__global__ void __launch_bounds__(256)
vq_output_kernel(const float* __restrict__ X, const float* __restrict__ W,
                 float* __restrict__ outq, float* __restrict__ oute) {
    const int tid = threadIdx.x;
    const int r0  = blockIdx.x * 64;
    double lsum = 0.0;
    for (int i = 0; i < 64; i++) {
        int r = r0 + i;
        int idx = g_idx[r];
        const float* x = X + (size_t)r * DIM;
        const float* w = W + (size_t)idx * DIM;
#pragma unroll
        for (int h = 0; h < 2; h++) {
            int c = tid + h * 256;
            float q = w[c], xv = x[c];
            float diff = q - xv;                 // fp32, matches reference
            outq[(size_t)r * DIM + c] = xv + diff;   // straight-through value
            lsum += (double)diff * (double)diff;
        }
#pragma unroll
        for (int h = 0; h < 4; h++) {
            int c = tid + h * 256;
            oute[(size_t)r * KCODES + c] = (c == idx) ? 1.0f : 0.0f;
        }
    }
#pragma unroll
    for (int o = 16; o > 0; o >>= 1) lsum += __shfl_down_sync(0xffffffffu, lsum, o);
    __shared__ double sd[8];
    if ((tid & 31) == 0) sd[tid >> 5] = lsum;
    __syncthreads();
    if (tid == 0) {
        double t = 0.0;
        for (int v = 0; v < 8; v++) t += sd[v];
        atomicAdd(&g_sse, t);
    }
}

// ============================================================
// finalize: loss + perplexity
// ============================================================
__global__ void vq_finalize_kernel(float* __restrict__ out) {
    __shared__ float red[32];
    int tid = threadIdx.x;
    float p = (float)g_counts[tid] / 65536.0f;      // exact (count / 2^16)
    float t = p * logf(p + 1e-10f);
#pragma unroll
    for (int o = 16; o > 0; o >>= 1) t += __shfl_down_sync(0xffffffffu, t, o);
    if ((tid & 31) == 0) red[tid >> 5] = t;
    __syncthreads();
    if (tid < 32) {
        float v = red[tid];
#pragma unroll
        for (int o = 16; o > 0; o >>= 1) v += __shfl_down_sync(0xffffffffu, v, o);
        if (tid == 0) {
            out[PERP_OFF] = expf(-v);
            float m = (float)(g_sse / 33554432.0);
            out[0] = m + 0.25f * m;                 // q_latent + 0.25*e_latent
        }
    }
}

// ============================================================
extern "C" void kernel_launch(void* const* d_in, const int* in_sizes, int n_in,
                              void* d_out, int out_size) {
    const float* X = (const float*)d_in[0];
    const float* W = (const float*)d_in[1];
    if (n_in >= 2 && in_sizes[0] == KCODES * DIM && in_sizes[1] == N_ROWS * DIM) {
        const float* t = X; X = W; W = t;   // defensive: input order swapped
    }
    float* out  = (float*)d_out;
    float* outq = out + QUANT_OFF;
    float* oute = out + ENC_OFF;

    cudaFuncSetAttribute(vq_argmin_kernel,
                         cudaFuncAttributeMaxDynamicSharedMemorySize,
                         SMEM_FLOATS * 4);

    vq_prep_kernel<<<128, 256>>>(W);
    vq_argmin_kernel<<<1024, 256, SMEM_FLOATS * 4>>>(X, W);
    vq_output_kernel<<<1024, 256>>>(X, W, outq, oute);
    vq_finalize_kernel<<<1, 1024>>>(out);
}